// round 10
// baseline (speedup 1.0000x reference)
#include <cuda_runtime.h>
#include <math.h>

// ---------------- problem constants ----------------
#define BB   16
#define CC   256
#define HIM  56
#define HW   3136            // 56*56
#define TOK  (BB*HW)         // 50176
#define NHD  8               // heads
#define HDD  32              // head dim
#define NWT  49              // tokens per window (7*7)
#define WINS 1024            // B * 64 windows
#define MLPD 1024

// ---------------- scratch (device globals; no cudaMalloc allowed) ----------------
__device__ __align__(256) float g_y [TOK*CC];     // shortcut (post pe_ln), later y after attn residual
__device__ __align__(256) float g_a [TOK*CC];     // LN outputs (n1 of y, later n2 of y)
__device__ __align__(256) float g_a2[TOK*CC];     // LN(n1) of y2
__device__ __align__(256) float g_q [TOK*CC];
__device__ __align__(256) float g_kv[TOK*2*CC];
__device__ __align__(256) float g_o [TOK*CC];     // embed pre-LN scratch, attn out, final pre-transpose
__device__ __align__(256) float g_h [TOK*MLPD];   // fc1/gelu output
__device__ __align__(256) float g_bias[NHD*NWT*NWT];

// ---------------- helpers ----------------
__device__ __forceinline__ float2 ffma2(float2 a, float2 b, float2 c) {
    unsigned long long ua = *reinterpret_cast<unsigned long long*>(&a);
    unsigned long long ub = *reinterpret_cast<unsigned long long*>(&b);
    unsigned long long uc = *reinterpret_cast<unsigned long long*>(&c);
    asm("fma.rn.f32x2 %0, %1, %2, %0;" : "+l"(uc) : "l"(ua), "l"(ub));
    return *reinterpret_cast<float2*>(&uc);
}

__device__ __forceinline__ float gelu_exact(float x) {
    return 0.5f * x * (1.0f + erff(x * 0.70710678118654752f));
}

// block (256 threads) reduction of (a,b) sums; red must have 16 floats
__device__ __forceinline__ float2 blockReduce2(float a, float b, float* red) {
    #pragma unroll
    for (int o = 16; o; o >>= 1) {
        a += __shfl_xor_sync(0xffffffffu, a, o);
        b += __shfl_xor_sync(0xffffffffu, b, o);
    }
    __syncthreads();                       // protect red from previous use
    int w = threadIdx.x >> 5;
    if ((threadIdx.x & 31) == 0) { red[w] = a; red[8 + w] = b; }
    __syncthreads();
    float ra = 0.f, rb = 0.f;
    #pragma unroll
    for (int i = 0; i < 8; i++) { ra += red[i]; rb += red[8 + i]; }
    return make_float2(ra, rb);
}

// ---------------- generic fp32 GEMM: C[m,n] = sum_k A[m,k]*W[n,k] + bias[n] (+epilogue) ----------
// A row-major M x K, W row-major N x K. M multiple of 128 (grid.y), N multiple of 128 (grid.x),
// K multiple of 16. EPI: 0 = bias only, 1 = bias + residual R[m,n], 2 = bias + exact GELU.
template<int EPI>
__global__ __launch_bounds__(256, 2) void gemm_f32(
    const float* __restrict__ A, const float* __restrict__ W,
    const float* __restrict__ bias, const float* __restrict__ R,
    float* __restrict__ C, int Nn, int K)
{
    __shared__ __align__(16) float As[16][128];
    __shared__ __align__(16) float Bs[16][128];
    const int tid = threadIdx.x;
    const int nt = blockIdx.x * 128;
    const int mt = blockIdx.y * 128;
    const int lr = tid >> 2;           // 0..63
    const int lk = (tid & 3) * 4;      // 0,4,8,12
    const float* Ap0 = A + (size_t)(mt + lr)      * K + lk;
    const float* Ap1 = A + (size_t)(mt + lr + 64) * K + lk;
    const float* Wp0 = W + (size_t)(nt + lr)      * K + lk;
    const float* Wp1 = W + (size_t)(nt + lr + 64) * K + lk;
    const int tx = tid & 15, ty = tid >> 4;

    float2 acc[8][4];
    #pragma unroll
    for (int i = 0; i < 8; i++)
        #pragma unroll
        for (int j = 0; j < 4; j++) acc[i][j] = make_float2(0.f, 0.f);

    float4 a0 = *(const float4*)Ap0;
    float4 a1 = *(const float4*)Ap1;
    float4 b0 = *(const float4*)Wp0;
    float4 b1 = *(const float4*)Wp1;

    for (int kt = 0; kt < K; kt += 16) {
        As[lk+0][lr]    = a0.x; As[lk+1][lr]    = a0.y; As[lk+2][lr]    = a0.z; As[lk+3][lr]    = a0.w;
        As[lk+0][lr+64] = a1.x; As[lk+1][lr+64] = a1.y; As[lk+2][lr+64] = a1.z; As[lk+3][lr+64] = a1.w;
        Bs[lk+0][lr]    = b0.x; Bs[lk+1][lr]    = b0.y; Bs[lk+2][lr]    = b0.z; Bs[lk+3][lr]    = b0.w;
        Bs[lk+0][lr+64] = b1.x; Bs[lk+1][lr+64] = b1.y; Bs[lk+2][lr+64] = b1.z; Bs[lk+3][lr+64] = b1.w;
        __syncthreads();
        if (kt + 16 < K) {   // prefetch next tile while computing current
            a0 = *(const float4*)(Ap0 + kt + 16);
            a1 = *(const float4*)(Ap1 + kt + 16);
            b0 = *(const float4*)(Wp0 + kt + 16);
            b1 = *(const float4*)(Wp1 + kt + 16);
        }
        #pragma unroll
        for (int k = 0; k < 16; k++) {
            float4 af0 = *(const float4*)&As[k][ty*8];
            float4 af1 = *(const float4*)&As[k][ty*8+4];
            float4 bf0 = *(const float4*)&Bs[k][tx*4];
            float4 bf1 = *(const float4*)&Bs[k][64+tx*4];
            float am[8] = {af0.x,af0.y,af0.z,af0.w,af1.x,af1.y,af1.z,af1.w};
            float2 bp[4] = {make_float2(bf0.x,bf0.y), make_float2(bf0.z,bf0.w),
                            make_float2(bf1.x,bf1.y), make_float2(bf1.z,bf1.w)};
            #pragma unroll
            for (int m = 0; m < 8; m++) {
                float2 ad = make_float2(am[m], am[m]);
                #pragma unroll
                for (int j = 0; j < 4; j++) acc[m][j] = ffma2(ad, bp[j], acc[m][j]);
            }
        }
        __syncthreads();
    }

    const float4 bq0 = *(const float4*)(bias + nt + tx*4);
    const float4 bq1 = *(const float4*)(bias + nt + 64 + tx*4);
    #pragma unroll
    for (int m = 0; m < 8; m++) {
        int row = mt + ty*8 + m;
        float4 v0 = make_float4(acc[m][0].x + bq0.x, acc[m][0].y + bq0.y,
                                acc[m][1].x + bq0.z, acc[m][1].y + bq0.w);
        float4 v1 = make_float4(acc[m][2].x + bq1.x, acc[m][2].y + bq1.y,
                                acc[m][3].x + bq1.z, acc[m][3].y + bq1.w);
        size_t o0 = (size_t)row * Nn + nt + tx*4;
        size_t o1 = o0 + 64;
        if (EPI == 1) {
            float4 r0 = *(const float4*)(R + o0);
            float4 r1 = *(const float4*)(R + o1);
            v0.x += r0.x; v0.y += r0.y; v0.z += r0.z; v0.w += r0.w;
            v1.x += r1.x; v1.y += r1.y; v1.z += r1.z; v1.w += r1.w;
        }
        if (EPI == 2) {
            v0.x = gelu_exact(v0.x); v0.y = gelu_exact(v0.y);
            v0.z = gelu_exact(v0.z); v0.w = gelu_exact(v0.w);
            v1.x = gelu_exact(v1.x); v1.y = gelu_exact(v1.y);
            v1.z = gelu_exact(v1.z); v1.w = gelu_exact(v1.w);
        }
        *(float4*)(C + o0) = v0;
        *(float4*)(C + o1) = v1;
    }
}

// ---------------- embed GEMM: y_pre[b*HW+hw, d] = sum_c x[b,c,hw]*pe_w[d,c] + pe_b[d] ----------
// A is K-major over tokens: A[k, m] = x[b*C*HW + k*HW + m]. grid (2, 25, 16), M=HW per batch.
__global__ __launch_bounds__(256, 2) void gemm_embed(
    const float* __restrict__ X, const float* __restrict__ W,
    const float* __restrict__ bias, float* __restrict__ C)
{
    __shared__ __align__(16) float As[16][128];
    __shared__ __align__(16) float Bs[16][128];
    const int tid = threadIdx.x;
    const int nt = blockIdx.x * 128;
    const int mt = blockIdx.y * 128;
    const int b  = blockIdx.z;
    const float* A = X + (size_t)b * CC * HW;

    const int lkE = tid >> 4;          // 0..15 (k row in tile)
    const int lmE = (tid & 15) * 8;    // 0..120 (m run)
    const bool mok = (mt + lmE) < HW;  // runs are entirely in or out (HW%8==0)
    const float* ApE = A + (size_t)lkE * HW + mt + lmE;

    const int lr = tid >> 2;
    const int lk = (tid & 3) * 4;
    const float* Wp0 = W + (size_t)(nt + lr)      * CC + lk;
    const float* Wp1 = W + (size_t)(nt + lr + 64) * CC + lk;
    const int tx = tid & 15, ty = tid >> 4;

    float2 acc[8][4];
    #pragma unroll
    for (int i = 0; i < 8; i++)
        #pragma unroll
        for (int j = 0; j < 4; j++) acc[i][j] = make_float2(0.f, 0.f);

    const float4 z4 = make_float4(0.f, 0.f, 0.f, 0.f);
    float4 a0 = mok ? *(const float4*)(ApE)     : z4;
    float4 a1 = mok ? *(const float4*)(ApE + 4) : z4;
    float4 b0 = *(const float4*)Wp0;
    float4 b1 = *(const float4*)Wp1;

    for (int kt = 0; kt < CC; kt += 16) {
        *(float4*)&As[lkE][lmE]     = a0;
        *(float4*)&As[lkE][lmE + 4] = a1;
        Bs[lk+0][lr]    = b0.x; Bs[lk+1][lr]    = b0.y; Bs[lk+2][lr]    = b0.z; Bs[lk+3][lr]    = b0.w;
        Bs[lk+0][lr+64] = b1.x; Bs[lk+1][lr+64] = b1.y; Bs[lk+2][lr+64] = b1.z; Bs[lk+3][lr+64] = b1.w;
        __syncthreads();
        if (kt + 16 < CC) {
            a0 = mok ? *(const float4*)(ApE + (size_t)(kt + 16) * HW)     : z4;
            a1 = mok ? *(const float4*)(ApE + (size_t)(kt + 16) * HW + 4) : z4;
            b0 = *(const float4*)(Wp0 + kt + 16);
            b1 = *(const float4*)(Wp1 + kt + 16);
        }
        #pragma unroll
        for (int k = 0; k < 16; k++) {
            float4 af0 = *(const float4*)&As[k][ty*8];
            float4 af1 = *(const float4*)&As[k][ty*8+4];
            float4 bf0 = *(const float4*)&Bs[k][tx*4];
            float4 bf1 = *(const float4*)&Bs[k][64+tx*4];
            float am[8] = {af0.x,af0.y,af0.z,af0.w,af1.x,af1.y,af1.z,af1.w};
            float2 bp[4] = {make_float2(bf0.x,bf0.y), make_float2(bf0.z,bf0.w),
                            make_float2(bf1.x,bf1.y), make_float2(bf1.z,bf1.w)};
            #pragma unroll
            for (int m = 0; m < 8; m++) {
                float2 ad = make_float2(am[m], am[m]);
                #pragma unroll
                for (int j = 0; j < 4; j++) acc[m][j] = ffma2(ad, bp[j], acc[m][j]);
            }
        }
        __syncthreads();
    }

    const float4 bq0 = *(const float4*)(bias + nt + tx*4);
    const float4 bq1 = *(const float4*)(bias + nt + 64 + tx*4);
    #pragma unroll
    for (int m = 0; m < 8; m++) {
        int mrow = mt + ty*8 + m;
        if (mrow < HW) {
            size_t row = (size_t)b * HW + mrow;
            float4 v0 = make_float4(acc[m][0].x + bq0.x, acc[m][0].y + bq0.y,
                                    acc[m][1].x + bq0.z, acc[m][1].y + bq0.w);
            float4 v1 = make_float4(acc[m][2].x + bq1.x, acc[m][2].y + bq1.y,
                                    acc[m][3].x + bq1.z, acc[m][3].y + bq1.w);
            *(float4*)(C + row * CC + nt + tx*4)      = v0;
            *(float4*)(C + row * CC + nt + 64 + tx*4) = v1;
        }
    }
}

// ---------------- fused double LayerNorm (pe_ln then n1) ----------------
__global__ __launch_bounds__(256) void dual_ln(
    const float* __restrict__ in,
    const float* __restrict__ w1, const float* __restrict__ b1,
    const float* __restrict__ w2, const float* __restrict__ b2,
    float* __restrict__ yOut, float* __restrict__ aOut)
{
    __shared__ float red[16];
    const size_t t = blockIdx.x;
    const int c = threadIdx.x;
    float v = in[t * CC + c];
    float2 s = blockReduce2(v, v * v, red);
    float mean = s.x * (1.f / CC);
    float var  = s.y * (1.f / CC) - mean * mean;
    float y = (v - mean) * rsqrtf(var + 1e-5f) * w1[c] + b1[c];
    if (yOut) yOut[t * CC + c] = y;
    float2 s2 = blockReduce2(y, y * y, red);
    float mean2 = s2.x * (1.f / CC);
    float var2  = s2.y * (1.f / CC) - mean2 * mean2;
    aOut[t * CC + c] = (y - mean2) * rsqrtf(var2 + 1e-5f) * w2[c] + b2[c];
}

__global__ __launch_bounds__(256) void ln_single(
    const float* __restrict__ in,
    const float* __restrict__ w, const float* __restrict__ b,
    float* __restrict__ outp)
{
    __shared__ float red[16];
    const size_t t = blockIdx.x;
    const int c = threadIdx.x;
    float v = in[t * CC + c];
    float2 s = blockReduce2(v, v * v, red);
    float mean = s.x * (1.f / CC);
    float var  = s.y * (1.f / CC) - mean * mean;
    outp[t * CC + c] = (v - mean) * rsqrtf(var + 1e-5f) * w[c] + b[c];
}

// ---------------- relative position bias expand: (NH, 49, 49) ----------------
__global__ void bias_kernel(const float* __restrict__ rel, float* __restrict__ bout)
{
    int idx = blockIdx.x * blockDim.x + threadIdx.x;
    if (idx >= NHD * NWT * NWT) return;
    int h  = idx / (NWT * NWT);
    int pq = idx % (NWT * NWT);
    int p = pq / NWT, q = pq % NWT;
    int i1 = p / 7, j1 = p % 7, i2 = q / 7, j2 = q % 7;
    int ridx = (i1 - i2 + 6) * 13 + (j1 - j2 + 6);
    bout[idx] = rel[ridx * NHD + h];
}

// ---------------- windowed attention: per (window, head) ----------------
__global__ __launch_bounds__(64) void attn_kernel(
    const float* __restrict__ q, const float* __restrict__ kv,
    const float* __restrict__ bias, float* __restrict__ o)
{
    __shared__ __align__(16) float qs[NWT * 32];
    __shared__ __align__(16) float ks[NWT * 32];
    __shared__ __align__(16) float vs[NWT * 32];
    __shared__ float ss[NWT * 51];   // pitch 51: conflict-free column access
    const int tid  = threadIdx.x;
    const int win  = blockIdx.x;
    const int head = blockIdx.y;
    const int b  = win >> 6;
    const int w6 = win & 63;
    const int t0 = b * HW + (w6 >> 3) * 7 * HIM + (w6 & 7) * 7;

    for (int idx = tid; idx < NWT * 32; idx += 64) {
        int n = idx >> 5, d = idx & 31;
        int t = t0 + (n / 7) * HIM + (n % 7);
        qs[idx] = q [(size_t)t * CC + head * 32 + d];
        ks[idx] = kv[(size_t)t * (2*CC) + head * 32 + d];
        vs[idx] = kv[(size_t)t * (2*CC) + CC + head * 32 + d];
    }
    __syncthreads();

    const int r = tid;
    if (r < NWT) {
        float4 qr[8];
        #pragma unroll
        for (int i = 0; i < 8; i++) qr[i] = ((const float4*)(qs + r * 32))[i];
        const float* brow = bias + head * (NWT * NWT) + r * NWT;
        float mx = -1e30f;
        for (int c = 0; c < NWT; c++) {
            const float4* kp = (const float4*)(ks + c * 32);
            float acc = 0.f;
            #pragma unroll
            for (int i = 0; i < 8; i++) {
                float4 kk = kp[i];
                acc += qr[i].x * kk.x + qr[i].y * kk.y + qr[i].z * kk.z + qr[i].w * kk.w;
            }
            float s = acc * 0.17677669529663687f + brow[c];
            ss[r * 51 + c] = s;
            mx = fmaxf(mx, s);
        }
        float sum = 0.f;
        for (int c = 0; c < NWT; c++) {
            float e = __expf(ss[r * 51 + c] - mx);
            ss[r * 51 + c] = e;
            sum += e;
        }
        float inv = 1.f / sum;
        float4 oa[8];
        #pragma unroll
        for (int i = 0; i < 8; i++) oa[i] = make_float4(0.f, 0.f, 0.f, 0.f);
        for (int c = 0; c < NWT; c++) {
            float p = ss[r * 51 + c];
            const float4* vp = (const float4*)(vs + c * 32);
            #pragma unroll
            for (int i = 0; i < 8; i++) {
                float4 vv = vp[i];
                oa[i].x += p * vv.x; oa[i].y += p * vv.y;
                oa[i].z += p * vv.z; oa[i].w += p * vv.w;
            }
        }
        int t = t0 + (r / 7) * HIM + (r % 7);
        float4* op = (float4*)(o + (size_t)t * CC + head * 32);
        #pragma unroll
        for (int i = 0; i < 8; i++) {
            oa[i].x *= inv; oa[i].y *= inv; oa[i].z *= inv; oa[i].w *= inv;
            op[i] = oa[i];
        }
    }
}

// ---------------- (B, HW, C) -> (B, C, HW) transpose ----------------
__global__ void transpose_out(const float* __restrict__ in, float* __restrict__ out)
{
    __shared__ float tile[32][33];
    const int b   = blockIdx.z;
    const int hw0 = blockIdx.x * 32;
    const int c0  = blockIdx.y * 32;
    #pragma unroll
    for (int i = 0; i < 4; i++) {
        int r = threadIdx.y + i * 8;
        tile[r][threadIdx.x] = in[((size_t)b * HW + hw0 + r) * CC + c0 + threadIdx.x];
    }
    __syncthreads();
    #pragma unroll
    for (int i = 0; i < 4; i++) {
        int r = threadIdx.y + i * 8;
        out[(size_t)b * CC * HW + (size_t)(c0 + r) * HW + hw0 + threadIdx.x] = tile[threadIdx.x][r];
    }
}

// ---------------- launch ----------------
extern "C" void kernel_launch(void* const* d_in, const int* in_sizes, int n_in,
                              void* d_out, int out_size)
{
    const float* x1      = (const float*)d_in[0];
    const float* x2      = (const float*)d_in[1];
    const float* pe_w    = (const float*)d_in[2];
    const float* pe_b    = (const float*)d_in[3];
    const float* pe_ln_w = (const float*)d_in[4];
    const float* pe_ln_b = (const float*)d_in[5];
    const float* n1_w    = (const float*)d_in[6];
    const float* n1_b    = (const float*)d_in[7];
    const float* q_w     = (const float*)d_in[8];
    const float* q_b     = (const float*)d_in[9];
    const float* kv_w    = (const float*)d_in[10];
    const float* kv_b    = (const float*)d_in[11];
    const float* relb    = (const float*)d_in[12];
    const float* proj_w  = (const float*)d_in[13];
    const float* proj_b  = (const float*)d_in[14];
    const float* n2_w    = (const float*)d_in[15];
    const float* n2_b    = (const float*)d_in[16];
    const float* fc1_w   = (const float*)d_in[17];
    const float* fc1_b   = (const float*)d_in[18];
    const float* fc2_w   = (const float*)d_in[19];
    const float* fc2_b   = (const float*)d_in[20];
    float* out = (float*)d_out;

    float *y, *a, *a2, *qb, *kvb, *ob, *hb, *bb;
    cudaGetSymbolAddress((void**)&y,  g_y);
    cudaGetSymbolAddress((void**)&a,  g_a);
    cudaGetSymbolAddress((void**)&a2, g_a2);
    cudaGetSymbolAddress((void**)&qb, g_q);
    cudaGetSymbolAddress((void**)&kvb,g_kv);
    cudaGetSymbolAddress((void**)&ob, g_o);
    cudaGetSymbolAddress((void**)&hb, g_h);
    cudaGetSymbolAddress((void**)&bb, g_bias);

    // embed x1 -> pre (ob), then fused pe_ln + n1 -> y (shortcut), a (attn input)
    gemm_embed<<<dim3(2, 25, BB), 256>>>(x1, pe_w, pe_b, ob);
    dual_ln<<<TOK, 256>>>(ob, pe_ln_w, pe_ln_b, n1_w, n1_b, y, a);
    // embed x2 -> pre (ob), fused LNs -> a2 only (y2 shortcut unused)
    gemm_embed<<<dim3(2, 25, BB), 256>>>(x2, pe_w, pe_b, ob);
    dual_ln<<<TOK, 256>>>(ob, pe_ln_w, pe_ln_b, n1_w, n1_b, nullptr, a2);

    // q / kv projections
    gemm_f32<0><<<dim3(2, TOK/128), 256>>>(a,  q_w,  q_b,  nullptr, qb,  CC,   CC);
    gemm_f32<0><<<dim3(4, TOK/128), 256>>>(a2, kv_w, kv_b, nullptr, kvb, 2*CC, CC);

    // relative position bias + attention
    bias_kernel<<<(NHD*NWT*NWT + 255)/256, 256>>>(relb, bb);
    attn_kernel<<<dim3(WINS, NHD), 64>>>(qb, kvb, bb, ob);

    // proj with residual (in-place on y)
    gemm_f32<1><<<dim3(2, TOK/128), 256>>>(ob, proj_w, proj_b, y, y, CC, CC);

    // MLP: LN -> fc1+GELU -> fc2 + residual
    ln_single<<<TOK, 256>>>(y, n2_w, n2_b, a);
    gemm_f32<2><<<dim3(8, TOK/128), 256>>>(a,  fc1_w, fc1_b, nullptr, hb, MLPD, CC);
    gemm_f32<1><<<dim3(2, TOK/128), 256>>>(hb, fc2_w, fc2_b, y, ob, CC, MLPD);

    // (B, HW, C) -> (B, C, H, W)
    transpose_out<<<dim3(HW/32, CC/32, BB), dim3(32, 8)>>>(ob, out);
}